// round 1
// baseline (speedup 1.0000x reference)
#include <cuda_runtime.h>

#define N_NODES 4096
#define N_EDGES 16384
#define NODE_DIM 128
#define HIDDEN 128
#define EDGE_DIM 64
#define HEADS 4
#define OUT_DIM 64
#define TCOLS (HEADS * HIDDEN)    /* 512 */
#define CATDIM (HEADS * EDGE_DIM) /* 256 */

// ---------------- scratch (static device globals; no allocation) ----------------
__device__ __align__(16) float g_T[N_NODES * TCOLS];      // 8 MB  [n][h*128+k]
__device__ __align__(16) float g_M[(size_t)N_EDGES * TCOLS]; // 32 MB [e][h*128+k]
__device__ __align__(16) float g_score[HEADS * N_EDGES];
__device__ __align__(16) float g_coeff[HEADS * N_EDGES];
__device__ __align__(16) float g_U[(size_t)N_EDGES * CATDIM]; // 16 MB [e][h*64+o]
__device__ unsigned g_mn_bits[CATDIM];
__device__ unsigned g_mx_bits[CATDIM];

// ordered-uint transform so unsigned atomicMin/Max order like floats
__device__ __forceinline__ unsigned f2ord(float f) {
    unsigned u = __float_as_uint(f);
    return (u & 0x80000000u) ? ~u : (u | 0x80000000u);
}
__device__ __forceinline__ float ord2f(unsigned o) {
    unsigned u = (o & 0x80000000u) ? (o & 0x7FFFFFFFu) : ~o;
    return __uint_as_float(u);
}

// ---------------- k0: reset min/max accumulators ----------------
__global__ void k0_init() {
    int t = threadIdx.x;
    if (t < CATDIM) {
        g_mn_bits[t] = 0xFFFFFFFFu; // ordered +inf
        g_mx_bits[t] = 0u;          // ordered -inf
    }
}

// ---------------- k1: T[n, h*128+k] = node @ W1[h] + b1[h] ----------------
// tiles 64(n) x 64(c), K=128 in steps of 16, 256 threads, 4x4 microtile
__global__ __launch_bounds__(256) void k1_node_transform(
    const float* __restrict__ node, const float* __restrict__ W1,
    const float* __restrict__ b1)
{
    __shared__ float As[16][64]; // [d][n]
    __shared__ float Bs[16][64]; // [d][c]
    const int t = threadIdx.x;
    const int n0 = blockIdx.x * 64;
    const int c0 = blockIdx.y * 64;
    const int h = c0 >> 7;
    const int k0 = c0 & 127;
    const int ty = t >> 4, tx = t & 15;
    float acc[4][4];
#pragma unroll
    for (int i = 0; i < 4; ++i)
#pragma unroll
        for (int j = 0; j < 4; ++j) acc[i][j] = 0.f;

    for (int d0 = 0; d0 < NODE_DIM; d0 += 16) {
        {   // A: node[n0+n][d0..d0+16) -> transposed
            int n = t >> 2, dq = (t & 3) * 4;
            float4 v = *(const float4*)&node[(n0 + n) * NODE_DIM + d0 + dq];
            As[dq + 0][n] = v.x; As[dq + 1][n] = v.y;
            As[dq + 2][n] = v.z; As[dq + 3][n] = v.w;
        }
        {   // B: W1[h][d0+d][k0+cq..]
            int d = t >> 4, cq = (t & 15) * 4;
            *(float4*)&Bs[d][cq] =
                *(const float4*)&W1[h * (NODE_DIM * HIDDEN) + (d0 + d) * HIDDEN + k0 + cq];
        }
        __syncthreads();
#pragma unroll
        for (int dd = 0; dd < 16; ++dd) {
            float a[4], b[4];
#pragma unroll
            for (int i = 0; i < 4; ++i) a[i] = As[dd][ty * 4 + i];
#pragma unroll
            for (int j = 0; j < 4; ++j) b[j] = Bs[dd][tx * 4 + j];
#pragma unroll
            for (int i = 0; i < 4; ++i)
#pragma unroll
                for (int j = 0; j < 4; ++j) acc[i][j] += a[i] * b[j];
        }
        __syncthreads();
    }
#pragma unroll
    for (int i = 0; i < 4; ++i)
#pragma unroll
        for (int j = 0; j < 4; ++j) {
            int c = c0 + tx * 4 + j;
            g_T[(size_t)(n0 + ty * 4 + i) * TCOLS + c] =
                acc[i][j] + b1[h * HIDDEN + k0 + tx * 4 + j];
        }
}

// ---------------- k2: M[e,c] = sum_n inc[n,e] * T[n,c]  (the big GEMM) ----------------
// 128x128 tile, BK=8, 256 threads, 8x8 microtile, double-buffered smem
__global__ __launch_bounds__(256, 2) void k2_edge_gemm(const float* __restrict__ inc)
{
    __shared__ float As[2][8][128];
    __shared__ float Bs[2][8][128];
    const int t = threadIdx.x;
    const int e0 = blockIdx.x * 128;
    const int c0 = blockIdx.y * 128;
    const int lr = t >> 5;          // 0..7
    const int lc = (t & 31) << 2;   // 0..124
    const int ty = t >> 4;          // 0..15
    const int tx = t & 15;

    {   // initial tile (kt = 0)
        *(float4*)&As[0][lr][lc] = *(const float4*)&inc[(size_t)lr * N_EDGES + e0 + lc];
        *(float4*)&Bs[0][lr][lc] = *(const float4*)&g_T[(size_t)lr * TCOLS + c0 + lc];
    }
    __syncthreads();

    float acc[8][8];
#pragma unroll
    for (int i = 0; i < 8; ++i)
#pragma unroll
        for (int j = 0; j < 8; ++j) acc[i][j] = 0.f;

    int buf = 0;
    for (int kt = 0; kt < N_NODES; kt += 8) {
        float4 an, bn;
        const bool pf = (kt + 8) < N_NODES;
        if (pf) {
            an = *(const float4*)&inc[(size_t)(kt + 8 + lr) * N_EDGES + e0 + lc];
            bn = *(const float4*)&g_T[(size_t)(kt + 8 + lr) * TCOLS + c0 + lc];
        }
#pragma unroll
        for (int kk = 0; kk < 8; ++kk) {
            float a[8], b[8];
            *(float4*)&a[0] = *(const float4*)&As[buf][kk][ty * 8];
            *(float4*)&a[4] = *(const float4*)&As[buf][kk][ty * 8 + 4];
            *(float4*)&b[0] = *(const float4*)&Bs[buf][kk][tx * 8];
            *(float4*)&b[4] = *(const float4*)&Bs[buf][kk][tx * 8 + 4];
#pragma unroll
            for (int i = 0; i < 8; ++i)
#pragma unroll
                for (int j = 0; j < 8; ++j) acc[i][j] += a[i] * b[j];
        }
        if (pf) {
            *(float4*)&As[buf ^ 1][lr][lc] = an;
            *(float4*)&Bs[buf ^ 1][lr][lc] = bn;
        }
        __syncthreads();
        buf ^= 1;
    }
#pragma unroll
    for (int i = 0; i < 8; ++i) {
        float* dst = &g_M[(size_t)(e0 + ty * 8 + i) * TCOLS + c0 + tx * 8];
        *(float4*)&dst[0] = make_float4(acc[i][0], acc[i][1], acc[i][2], acc[i][3]);
        *(float4*)&dst[4] = make_float4(acc[i][4], acc[i][5], acc[i][6], acc[i][7]);
    }
}

// ---------------- k3: scores[h,e] = leaky_relu(M[e,h*128:]·Wa[h] + ba[h]) ----------------
__global__ void k3_scores(const float* __restrict__ Wa, const float* __restrict__ ba)
{
    int warp = (blockIdx.x * blockDim.x + threadIdx.x) >> 5;
    int lane = threadIdx.x & 31;
    int h = warp >> 14;
    int e = warp & (N_EDGES - 1);
    const float* mrow = &g_M[(size_t)e * TCOLS + h * HIDDEN];
    const float* wa = &Wa[h * HIDDEN];
    float v = mrow[lane] * wa[lane]
            + mrow[lane + 32] * wa[lane + 32]
            + mrow[lane + 64] * wa[lane + 64]
            + mrow[lane + 96] * wa[lane + 96];
#pragma unroll
    for (int o = 16; o > 0; o >>= 1) v += __shfl_xor_sync(0xffffffffu, v, o);
    if (lane == 0) {
        float s = v + ba[h];
        s = s > 0.f ? s : 0.2f * s;  // leaky relu, slope 0.2
        g_score[h * N_EDGES + e] = s;
    }
}

// ---------------- k4: softmax over edges, per head ----------------
__global__ void k4_softmax()
{
    __shared__ float red[1024];
    const int h = blockIdx.x;
    const int t = threadIdx.x;
    const float* srow = &g_score[h * N_EDGES];

    float m = -3.4e38f;
    for (int i = t; i < N_EDGES; i += 1024) m = fmaxf(m, srow[i]);
    red[t] = m;
    __syncthreads();
    for (int s = 512; s > 0; s >>= 1) {
        if (t < s) red[t] = fmaxf(red[t], red[t + s]);
        __syncthreads();
    }
    m = red[0];
    __syncthreads();

    float sum = 0.f;
    for (int i = t; i < N_EDGES; i += 1024) sum += expf(srow[i] - m);
    red[t] = sum;
    __syncthreads();
    for (int s = 512; s > 0; s >>= 1) {
        if (t < s) red[t] += red[t + s];
        __syncthreads();
    }
    float inv = 1.0f / red[0];

    for (int i = t; i < N_EDGES; i += 1024)
        g_coeff[h * N_EDGES + i] = expf(srow[i] - m) * inv;
}

// ---------------- k5: U[e,h*64+o] = coeff*(M@W2) + b2 ; column min/max ----------------
// block: 32 edges x one head; smem: W2 (32KB) + M tile (16KB) = 48KB
__global__ __launch_bounds__(256) void k5_u(const float* __restrict__ W2,
                                            const float* __restrict__ b2)
{
    __shared__ float sW2[HIDDEN * EDGE_DIM]; // [k][o]
    __shared__ float sM[32 * HIDDEN];        // [e][k], later reused as u tile [32][64]
    const int t = threadIdx.x;
    const int e0 = blockIdx.x * 32;
    const int h = blockIdx.y;

    for (int i = t; i < HIDDEN * EDGE_DIM / 4; i += 256)
        *(float4*)&sW2[i * 4] = *(const float4*)&W2[h * HIDDEN * EDGE_DIM + i * 4];
    for (int i = t; i < 32 * HIDDEN / 4; i += 256) {
        int l = i * 4; int e = l >> 7; int k = l & 127;
        *(float4*)&sM[l] = *(const float4*)&g_M[(size_t)(e0 + e) * TCOLS + h * HIDDEN + k];
    }
    __syncthreads();

    const int ty = t >> 4, tx = t & 15;
    float acc[2][4] = {{0.f,0.f,0.f,0.f},{0.f,0.f,0.f,0.f}};
    for (int k = 0; k < HIDDEN; ++k) {
        float4 w = *(const float4*)&sW2[k * EDGE_DIM + tx * 4];
#pragma unroll
        for (int ee = 0; ee < 2; ++ee) {
            float mv = sM[(ty + ee * 16) * HIDDEN + k];
            acc[ee][0] += mv * w.x; acc[ee][1] += mv * w.y;
            acc[ee][2] += mv * w.z; acc[ee][3] += mv * w.w;
        }
    }
    float uv[2][4];
#pragma unroll
    for (int ee = 0; ee < 2; ++ee) {
        int e = ty + ee * 16;
        float cf = g_coeff[h * N_EDGES + e0 + e];
#pragma unroll
        for (int j = 0; j < 4; ++j)
            uv[ee][j] = cf * acc[ee][j] + b2[h * EDGE_DIM + tx * 4 + j];
    }
    __syncthreads(); // all reads of sM done before overwrite
#pragma unroll
    for (int ee = 0; ee < 2; ++ee) {
        int e = ty + ee * 16;
#pragma unroll
        for (int j = 0; j < 4; ++j) {
            sM[e * EDGE_DIM + tx * 4 + j] = uv[ee][j];
            g_U[(size_t)(e0 + e) * CATDIM + h * EDGE_DIM + tx * 4 + j] = uv[ee][j];
        }
    }
    __syncthreads();
    if (t < EDGE_DIM) {
        float mn = 3.4e38f, mx = -3.4e38f;
        for (int e = 0; e < 32; ++e) {
            float v = sM[e * EDGE_DIM + t];
            mn = fminf(mn, v); mx = fmaxf(mx, v);
        }
        atomicMin(&g_mn_bits[h * EDGE_DIM + t], f2ord(mn));
        atomicMax(&g_mx_bits[h * EDGE_DIM + t], f2ord(mx));
    }
}

// ---------------- k6: out = relu(minmax_norm(U)) @ Wout + bout ----------------
// block: 32 edges; normalized x tile in smem (32KB); Wout via L1
__global__ __launch_bounds__(256) void k6_out(const float* __restrict__ Wout,
                                              const float* __restrict__ bout,
                                              float* __restrict__ out)
{
    __shared__ float sX[32 * CATDIM];
    __shared__ float sMin[CATDIM];
    __shared__ float sInv[CATDIM];
    const int t = threadIdx.x;
    const int e0 = blockIdx.x * 32;

    for (int i = t; i < CATDIM; i += 256) {
        float mn = ord2f(g_mn_bits[i]);
        float mx = ord2f(g_mx_bits[i]);
        sMin[i] = mn;
        sInv[i] = 1.0f / (mx - mn + 1e-8f);
    }
    __syncthreads();
    for (int i = t; i < 32 * CATDIM / 4; i += 256) {
        int l = i * 4; int e = l >> 8; int c = l & 255;
        float4 v = *(const float4*)&g_U[(size_t)(e0 + e) * CATDIM + c];
        v.x = fmaxf((v.x - sMin[c + 0]) * sInv[c + 0], 0.f);
        v.y = fmaxf((v.y - sMin[c + 1]) * sInv[c + 1], 0.f);
        v.z = fmaxf((v.z - sMin[c + 2]) * sInv[c + 2], 0.f);
        v.w = fmaxf((v.w - sMin[c + 3]) * sInv[c + 3], 0.f);
        *(float4*)&sX[l] = v;
    }
    __syncthreads();

    const int ty = t >> 4, tx = t & 15;
    float acc[2][4] = {{0.f,0.f,0.f,0.f},{0.f,0.f,0.f,0.f}};
#pragma unroll 4
    for (int c = 0; c < CATDIM; ++c) {
        float4 w = *(const float4*)&Wout[c * OUT_DIM + tx * 4];
#pragma unroll
        for (int ee = 0; ee < 2; ++ee) {
            float xv = sX[(ty + ee * 16) * CATDIM + c];
            acc[ee][0] += xv * w.x; acc[ee][1] += xv * w.y;
            acc[ee][2] += xv * w.z; acc[ee][3] += xv * w.w;
        }
    }
    float4 bo = *(const float4*)&bout[tx * 4];
#pragma unroll
    for (int ee = 0; ee < 2; ++ee) {
        int e = e0 + ty + ee * 16;
        out[(size_t)e * OUT_DIM + tx * 4 + 0] = acc[ee][0] + bo.x;
        out[(size_t)e * OUT_DIM + tx * 4 + 1] = acc[ee][1] + bo.y;
        out[(size_t)e * OUT_DIM + tx * 4 + 2] = acc[ee][2] + bo.z;
        out[(size_t)e * OUT_DIM + tx * 4 + 3] = acc[ee][3] + bo.w;
    }
}

// ---------------- launch ----------------
extern "C" void kernel_launch(void* const* d_in, const int* in_sizes, int n_in,
                              void* d_out, int out_size)
{
    (void)in_sizes; (void)n_in; (void)out_size;
    const float* node = (const float*)d_in[0];
    const float* inc  = (const float*)d_in[1];
    const float* W1   = (const float*)d_in[2];
    const float* b1   = (const float*)d_in[3];
    const float* Wa   = (const float*)d_in[4];
    const float* ba   = (const float*)d_in[5];
    const float* W2   = (const float*)d_in[6];
    const float* b2   = (const float*)d_in[7];
    const float* Wout = (const float*)d_in[8];
    const float* bout = (const float*)d_in[9];
    float* out = (float*)d_out;

    k0_init<<<1, 256>>>();
    k1_node_transform<<<dim3(N_NODES / 64, TCOLS / 64), 256>>>(node, W1, b1);
    k2_edge_gemm<<<dim3(N_EDGES / 128, TCOLS / 128), 256>>>(inc);
    k3_scores<<<(HEADS * N_EDGES) / 8, 256>>>(Wa, ba);
    k4_softmax<<<HEADS, 1024>>>();
    k5_u<<<dim3(N_EDGES / 32, HEADS), 256>>>(W2, b2);
    k6_out<<<N_EDGES / 32, 256>>>(Wout, bout, out);
}

// round 4
// speedup vs baseline: 3.7415x; 3.7415x over previous
#include <cuda_runtime.h>
#include <cuda_fp16.h>
#include <cstdint>
#include <cstddef>

#define N_NODES 4096
#define N_EDGES 16384
#define NODE_DIM 128
#define HIDDEN 128
#define EDGE_DIM 64
#define HEADS 4
#define OUT_DIM 64
#define TCOLS (HEADS * HIDDEN)    /* 512 */
#define CATDIM (HEADS * EDGE_DIM) /* 256 */
#define NB 272                    /* B cols: 256 P + 4 q + 12 zero pad */

// ---------------- scratch (static device globals; no allocation) ----------------
__device__ __align__(16) float g_t[(size_t)N_NODES * TCOLS];          // 8 MB
__device__ __align__(16) __half g_Bhi[(size_t)NB * N_NODES];          // 2.2 MB [c][n]
__device__ __align__(16) __half g_Blo[(size_t)NB * N_NODES];
__device__ __align__(16) float g_Mu[(size_t)N_EDGES * CATDIM];        // 16.8 MB [e][c]
__device__ __align__(16) float g_score[HEADS * N_EDGES];
__device__ __align__(16) float g_coeff[HEADS * N_EDGES];
__device__ __align__(16) float g_U[(size_t)N_EDGES * CATDIM];         // 16.8 MB
__device__ unsigned g_mn_bits[CATDIM];
__device__ unsigned g_mx_bits[CATDIM];

// ---------------- helpers ----------------
__device__ __forceinline__ uint32_t smem_u32(const void* p) {
    uint32_t a;
    asm("{ .reg .u64 t; cvta.to.shared.u64 t, %1; cvt.u32.u64 %0, t; }" : "=r"(a) : "l"(p));
    return a;
}
__device__ __forceinline__ void cp16(uint32_t dst, const void* src) {
    asm volatile("cp.async.cg.shared.global [%0], [%1], 16;" :: "r"(dst), "l"(src));
}
__device__ __forceinline__ void ldmat4t(uint32_t (&r)[4], uint32_t addr) {
    asm volatile("ldmatrix.sync.aligned.m8n8.x4.trans.shared.b16 {%0,%1,%2,%3}, [%4];"
                 : "=r"(r[0]), "=r"(r[1]), "=r"(r[2]), "=r"(r[3]) : "r"(addr));
}
__device__ __forceinline__ void hmma(float (&d)[4], const uint32_t (&a)[4],
                                     uint32_t b0, uint32_t b1) {
    asm volatile("mma.sync.aligned.m16n8k16.row.col.f32.f16.f16.f32 "
                 "{%0,%1,%2,%3}, {%4,%5,%6,%7}, {%8,%9}, {%0,%1,%2,%3};"
                 : "+f"(d[0]), "+f"(d[1]), "+f"(d[2]), "+f"(d[3])
                 : "r"(a[0]), "r"(a[1]), "r"(a[2]), "r"(a[3]), "r"(b0), "r"(b1));
}
__device__ __forceinline__ unsigned f2ord(float f) {
    unsigned u = __float_as_uint(f);
    return (u & 0x80000000u) ? ~u : (u | 0x80000000u);
}
__device__ __forceinline__ float ord2f(unsigned o) {
    unsigned u = (o & 0x80000000u) ? (o & 0x7FFFFFFFu) : ~o;
    return __uint_as_float(u);
}

// ---------------- k0: init minmax + zero pad rows of B ----------------
__global__ void k0_init() {
    int idx = blockIdx.x * blockDim.x + threadIdx.x;
    if (idx < CATDIM) { g_mn_bits[idx] = 0xFFFFFFFFu; g_mx_bits[idx] = 0u; }
    const __half z = __float2half(0.f);
    for (size_t i = idx; i < (size_t)12 * N_NODES; i += (size_t)gridDim.x * blockDim.x) {
        g_Bhi[(size_t)260 * N_NODES + i] = z;
        g_Blo[(size_t)260 * N_NODES + i] = z;
    }
}

// ---------------- k1: t[n, h*128+k] = node @ W1[h] + b1[h] (fp32) ----------------
__global__ __launch_bounds__(256) void k1_node_transform(
    const float* __restrict__ node, const float* __restrict__ W1,
    const float* __restrict__ b1)
{
    __shared__ float As[16][64];
    __shared__ float Bs[16][64];
    const int t = threadIdx.x;
    const int n0 = blockIdx.x * 64;
    const int c0 = blockIdx.y * 64;
    const int h = c0 >> 7;
    const int k0 = c0 & 127;
    const int ty = t >> 4, tx = t & 15;
    float acc[4][4];
#pragma unroll
    for (int i = 0; i < 4; ++i)
#pragma unroll
        for (int j = 0; j < 4; ++j) acc[i][j] = 0.f;

    for (int d0 = 0; d0 < NODE_DIM; d0 += 16) {
        {
            int n = t >> 2, dq = (t & 3) * 4;
            float4 v = *(const float4*)&node[(n0 + n) * NODE_DIM + d0 + dq];
            As[dq + 0][n] = v.x; As[dq + 1][n] = v.y;
            As[dq + 2][n] = v.z; As[dq + 3][n] = v.w;
        }
        {
            int d = t >> 4, cq = (t & 15) * 4;
            *(float4*)&Bs[d][cq] =
                *(const float4*)&W1[h * (NODE_DIM * HIDDEN) + (d0 + d) * HIDDEN + k0 + cq];
        }
        __syncthreads();
#pragma unroll
        for (int dd = 0; dd < 16; ++dd) {
            float a[4], b[4];
#pragma unroll
            for (int i = 0; i < 4; ++i) a[i] = As[dd][ty * 4 + i];
#pragma unroll
            for (int j = 0; j < 4; ++j) b[j] = Bs[dd][tx * 4 + j];
#pragma unroll
            for (int i = 0; i < 4; ++i)
#pragma unroll
                for (int j = 0; j < 4; ++j) acc[i][j] += a[i] * b[j];
        }
        __syncthreads();
    }
#pragma unroll
    for (int i = 0; i < 4; ++i)
#pragma unroll
        for (int j = 0; j < 4; ++j)
            g_t[(size_t)(n0 + ty * 4 + i) * TCOLS + c0 + tx * 4 + j] =
                acc[i][j] + b1[h * HIDDEN + k0 + tx * 4 + j];
}

// ---------------- k1b: P = t@W2 (no b2), q = t.Wa; write split-fp16 transposed ----------------
__global__ __launch_bounds__(256) void k1b_project(
    const float* __restrict__ W2, const float* __restrict__ Wa)
{
    extern __shared__ float smf[];
    float* sT = smf;                 // [64][132]
    float* sW2 = smf + 64 * 132;     // [128][68]
    float* sWa = sW2 + 128 * 68;     // [128]
    const int t = threadIdx.x;
    const int n0 = blockIdx.x * 64;
    const int h = blockIdx.y;

    for (int i = t; i < 64 * 32; i += 256) {
        int n = i >> 5, k4 = (i & 31) * 4;
        *(float4*)&sT[n * 132 + k4] =
            *(const float4*)&g_t[(size_t)(n0 + n) * TCOLS + h * HIDDEN + k4];
    }
    for (int i = t; i < 128 * 16; i += 256) {
        int k = i >> 4, o4 = (i & 15) * 4;
        *(float4*)&sW2[k * 68 + o4] =
            *(const float4*)&W2[(size_t)h * HIDDEN * EDGE_DIM + k * EDGE_DIM + o4];
    }
    if (t < 128) sWa[t] = Wa[h * HIDDEN + t];
    __syncthreads();

    const int ty = t >> 4, tx = t & 15;
    float acc[4][4] = {};
    for (int k = 0; k < HIDDEN; ++k) {
        float4 w = *(const float4*)&sW2[k * 68 + tx * 4];
#pragma unroll
        for (int i = 0; i < 4; ++i) {
            float a = sT[(ty * 4 + i) * 132 + k];
            acc[i][0] += a * w.x; acc[i][1] += a * w.y;
            acc[i][2] += a * w.z; acc[i][3] += a * w.w;
        }
    }
#pragma unroll
    for (int j = 0; j < 4; ++j) {
        int c = h * EDGE_DIM + tx * 4 + j;
        __half hh[4], hl[4];
#pragma unroll
        for (int i = 0; i < 4; ++i) {
            hh[i] = __float2half_rn(acc[i][j]);
            hl[i] = __float2half_rn(acc[i][j] - __half2float(hh[i]));
        }
        size_t off = (size_t)c * N_NODES + n0 + ty * 4;
        *(__half2*)&g_Bhi[off]     = __halves2half2(hh[0], hh[1]);
        *(__half2*)&g_Bhi[off + 2] = __halves2half2(hh[2], hh[3]);
        *(__half2*)&g_Blo[off]     = __halves2half2(hl[0], hl[1]);
        *(__half2*)&g_Blo[off + 2] = __halves2half2(hl[2], hl[3]);
    }
    if (tx == 0) {
#pragma unroll
        for (int i = 0; i < 4; ++i) {
            int n = ty * 4 + i;
            float q = 0.f;
            for (int k = 0; k < HIDDEN; ++k) q += sT[n * 132 + k] * sWa[k];
            __half qh = __float2half_rn(q);
            __half ql = __float2half_rn(q - __half2float(qh));
            g_Bhi[(size_t)(CATDIM + h) * N_NODES + n0 + n] = qh;
            g_Blo[(size_t)(CATDIM + h) * N_NODES + n0 + n] = ql;
        }
    }
}

// ---------------- k2: HMMA split-fp16 GEMM  Mu[e, 0..259] = incT @ [P|q] ----------------
// CTA: 128 e x 272 cols, K chunks of 32, 2-stage pipeline.
// smem per stage: A_hi/A_lo [32][136] halves (8704B each), B_hi/B_lo [272][40] halves (21760B each)
#define K2_SS 60928
#define K2_OFF_AL 8704
#define K2_OFF_BH 17408
#define K2_OFF_BL 39168
#define K2_SMEM (2 * K2_SS)
#define NCHUNK (N_NODES / 32)

__global__ __launch_bounds__(256, 1) void k2_mma(const float* __restrict__ inc,
                                                 const float* __restrict__ ba)
{
    extern __shared__ char sm[];
    const int t = threadIdx.x;
    const int lane = t & 31, wid = t >> 5;
    const int e0 = blockIdx.x * 128;
    const int wm0 = (wid >> 1) * 32;   // warp m offset (4 warps in m)
    const int wn0 = (wid & 1) * 136;   // warp n offset (2 warps in n)
    const uint32_t sb = smem_u32(sm);

    float4 rA[4];
    // ---- A global prefetch (inc rows kt*32..+32, cols e0..e0+128) ----
    auto ldgA = [&](int kt) {
#pragma unroll
        for (int it = 0; it < 4; ++it) {
            int idx = t + it * 256;
            int r = idx >> 5, f = idx & 31;
            rA[it] = *(const float4*)&inc[(size_t)(kt * 32 + r) * N_EDGES + e0 + f * 4];
        }
    };
    // ---- A convert + store to smem [k][m] halves ----
    auto stsA = [&](int s) {
        char* ah = sm + s * K2_SS;
        char* al = sm + s * K2_SS + K2_OFF_AL;
#pragma unroll
        for (int it = 0; it < 4; ++it) {
            int idx = t + it * 256;
            int r = idx >> 5, f = idx & 31;
            float4 v = rA[it];
            __half hx = __float2half_rn(v.x), hy = __float2half_rn(v.y);
            __half hz = __float2half_rn(v.z), hw = __float2half_rn(v.w);
            __half lx = __float2half_rn(v.x - __half2float(hx));
            __half ly = __float2half_rn(v.y - __half2float(hy));
            __half lz = __float2half_rn(v.z - __half2float(hz));
            __half lw = __float2half_rn(v.w - __half2float(hw));
            uint32_t off = r * 272 + f * 8;  // bytes: row stride 136 halves
            *(__half2*)(ah + off)     = __halves2half2(hx, hy);
            *(__half2*)(ah + off + 4) = __halves2half2(hz, hw);
            *(__half2*)(al + off)     = __halves2half2(lx, ly);
            *(__half2*)(al + off + 4) = __halves2half2(lz, lw);
        }
    };
    // ---- B cp.async: rows 0..271, 64B each from g_Bhi/g_Blo ----
    auto cpB = [&](int s, int kt) {
        uint32_t bh = sb + s * K2_SS + K2_OFF_BH;
        uint32_t bl = sb + s * K2_SS + K2_OFF_BL;
        const char* ph = (const char*)g_Bhi;
        const char* pl = (const char*)g_Blo;
#pragma unroll
        for (int i = t; i < 1088; i += 256) {
            int r = i >> 2, j = i & 3;
            size_t g = ((size_t)r * N_NODES + kt * 32) * 2 + j * 16;
            uint32_t d = r * 80 + j * 16;
            cp16(bh + d, ph + g);
            cp16(bl + d, pl + g);
        }
        asm volatile("cp.async.commit_group;" ::: "memory");
    };

    float acc[2][17][4];
#pragma unroll
    for (int mt = 0; mt < 2; ++mt)
#pragma unroll
        for (int nt = 0; nt < 17; ++nt)
#pragma unroll
            for (int j = 0; j < 4; ++j) acc[mt][nt][j] = 0.f;

    // prologue
    ldgA(0);
    cpB(0, 0);
    stsA(0);
    ldgA(1);

    const int grp = lane >> 3, gi = lane & 7;
    for (int kt = 0; kt < NCHUNK; ++kt) {
        const int buf = kt & 1;
        __syncthreads();  // everyone done with buf^1's previous chunk
        if (kt + 1 < NCHUNK) {
            cpB(buf ^ 1, kt + 1);
            stsA(buf ^ 1);
            if (kt + 2 < NCHUNK) ldgA(kt + 2);
            asm volatile("cp.async.wait_group 1;" ::: "memory");
        } else {
            asm volatile("cp.async.wait_group 0;" ::: "memory");
        }
        __syncthreads();

        const uint32_t aBase = sb + buf * K2_SS;
        const char* bBase = sm + buf * K2_SS + K2_OFF_BH;
        const char* blBase = sm + buf * K2_SS + K2_OFF_BL;
#pragma unroll
        for (int kk = 0; kk < 32; kk += 16) {
            uint32_t aH[2][4], aL[2][4];
            const int krow = kk + ((grp & 2) ? 8 : 0) + gi;
#pragma unroll
            for (int mt = 0; mt < 2; ++mt) {
                const uint32_t mcol = wm0 + mt * 16 + ((grp & 1) ? 8 : 0);
                ldmat4t(aH[mt], aBase + krow * 272 + mcol * 2);
                ldmat4t(aL[mt], aBase + K2_OFF_AL + krow * 272 + mcol * 2);
            }
            const int koff = (kk + (lane & 3) * 2) * 2;  // bytes
#pragma unroll
            for (int nt = 0; nt < 17; ++nt) {
                const int n = wn0 + nt * 8 + (lane >> 2);
                uint32_t bh0 = *(const uint32_t*)(bBase + n * 80 + koff);
                uint32_t bh1 = *(const uint32_t*)(bBase + n * 80 + koff + 16);
                uint32_t bl0 = *(const uint32_t*)(blBase + n * 80 + koff);
                uint32_t bl1 = *(const uint32_t*)(blBase + n * 80 + koff + 16);
#pragma unroll
                for (int mt = 0; mt < 2; ++mt) {
                    hmma(acc[mt][nt], aH[mt], bh0, bh1);
                    hmma(acc[mt][nt], aH[mt], bl0, bl1);
                    hmma(acc[mt][nt], aL[mt], bh0, bh1);
                }
            }
        }
    }

    // epilogue
#pragma unroll
    for (int mt = 0; mt < 2; ++mt) {
        const int e = e0 + wm0 + mt * 16 + (lane >> 2);
#pragma unroll
        for (int nt = 0; nt < 17; ++nt) {
            const int c = wn0 + nt * 8 + (lane & 3) * 2;
            if (c < CATDIM) {
                *(float2*)&g_Mu[(size_t)e * CATDIM + c] =
                    make_float2(acc[mt][nt][0], acc[mt][nt][1]);
                *(float2*)&g_Mu[(size_t)(e + 8) * CATDIM + c] =
                    make_float2(acc[mt][nt][2], acc[mt][nt][3]);
            } else if (c < CATDIM + HEADS) {
                const int h0 = c - CATDIM;
                float b0 = ba[h0], b1 = ba[h0 + 1];
                float s0 = acc[mt][nt][0] + b0, s1 = acc[mt][nt][1] + b1;
                float s2 = acc[mt][nt][2] + b0, s3 = acc[mt][nt][3] + b1;
                s0 = s0 > 0.f ? s0 : 0.2f * s0;
                s1 = s1 > 0.f ? s1 : 0.2f * s1;
                s2 = s2 > 0.f ? s2 : 0.2f * s2;
                s3 = s3 > 0.f ? s3 : 0.2f * s3;
                g_score[h0 * N_EDGES + e] = s0;
                g_score[(h0 + 1) * N_EDGES + e] = s1;
                g_score[h0 * N_EDGES + e + 8] = s2;
                g_score[(h0 + 1) * N_EDGES + e + 8] = s3;
            }
        }
    }
}

// ---------------- k4: softmax over edges, per head ----------------
__global__ void k4_softmax()
{
    __shared__ float red[1024];
    const int h = blockIdx.x;
    const int t = threadIdx.x;
    const float* srow = &g_score[h * N_EDGES];

    float m = -3.4e38f;
    for (int i = t; i < N_EDGES; i += 1024) m = fmaxf(m, srow[i]);
    red[t] = m;
    __syncthreads();
    for (int s = 512; s > 0; s >>= 1) {
        if (t < s) red[t] = fmaxf(red[t], red[t + s]);
        __syncthreads();
    }
    m = red[0];
    __syncthreads();

    float sum = 0.f;
    for (int i = t; i < N_EDGES; i += 1024) sum += expf(srow[i] - m);
    red[t] = sum;
    __syncthreads();
    for (int s = 512; s > 0; s >>= 1) {
        if (t < s) red[t] += red[t + s];
        __syncthreads();
    }
    float inv = 1.0f / red[0];

    for (int i = t; i < N_EDGES; i += 1024)
        g_coeff[h * N_EDGES + i] = expf(srow[i] - m) * inv;
}

// ---------------- k5: u = coeff*Mu + b2 ; column min/max ----------------
__global__ __launch_bounds__(256) void k5_u(const float* __restrict__ b2)
{
    const int c = threadIdx.x;
    const int e0 = blockIdx.x * 64;
    const int h = c >> 6;
    const float bb = b2[c];
    float mn = 3.4e38f, mx = -3.4e38f;
    for (int i = 0; i < 64; ++i) {
        int e = e0 + i;
        float u = g_coeff[h * N_EDGES + e] * g_Mu[(size_t)e * CATDIM + c] + bb;
        g_U[(size_t)e * CATDIM + c] = u;
        mn = fminf(mn, u); mx = fmaxf(mx, u);
    }
    atomicMin(&g_mn_bits[c], f2ord(mn));
    atomicMax(&g_mx_bits[c], f2ord(mx));
}

// ---------------- k6: out = relu(minmax_norm(U)) @ Wout + bout ----------------
__global__ __launch_bounds__(256) void k6_out(const float* __restrict__ Wout,
                                              const float* __restrict__ bout,
                                              float* __restrict__ out)
{
    __shared__ float sX[32 * CATDIM];
    __shared__ float sMin[CATDIM];
    __shared__ float sInv[CATDIM];
    const int t = threadIdx.x;
    const int e0 = blockIdx.x * 32;

    for (int i = t; i < CATDIM; i += 256) {
        float mn = ord2f(g_mn_bits[i]);
        float mx = ord2f(g_mx_bits[i]);
        sMin[i] = mn;
        sInv[i] = 1.0f / (mx - mn + 1e-8f);
    }
    __syncthreads();
    for (int i = t; i < 32 * CATDIM / 4; i += 256) {
        int l = i * 4; int e = l >> 8; int c = l & 255;
        float4 v = *(const float4*)&g_U[(size_t)(e0 + e) * CATDIM + c];
        v.x = fmaxf((v.x - sMin[c + 0]) * sInv[c + 0], 0.f);
        v.y = fmaxf((v.y - sMin[c + 1]) * sInv[c + 1], 0.f);
        v.z = fmaxf((v.z - sMin[c + 2]) * sInv[c + 2], 0.f);
        v.w = fmaxf((v.w - sMin[c + 3]) * sInv[c + 3], 0.f);
        *(float4*)&sX[l] = v;
    }
    __syncthreads();

    const int ty = t >> 4, tx = t & 15;
    float acc[2][4] = {{0.f,0.f,0.f,0.f},{0.f,0.f,0.f,0.f}};
#pragma unroll 4
    for (int c = 0; c < CATDIM; ++c) {
        float4 w = *(const float4*)&Wout[c * OUT_DIM + tx * 4];
#pragma unroll
        for (int ee = 0; ee < 2; ++ee) {
            float xv = sX[(ty + ee * 16) * CATDIM + c];
            acc[ee][0] += xv * w.x; acc[ee][1] += xv * w.y;
            acc[ee][2] += xv * w.z; acc[ee][3] += xv * w.w;
        }
    }
    float4 bo = *(const float4*)&bout[tx * 4];
#pragma unroll
    for (int ee = 0; ee < 2; ++ee) {
        int e = e0 + ty + ee * 16;
        out[(size_t)e * OUT_DIM + tx * 4 + 0] = acc[ee][0] + bo.x;
        out[(size_t)e * OUT_DIM + tx * 4 + 1] = acc[ee][1] + bo.y;
        out[(size_t)e * OUT_DIM + tx * 4 + 2] = acc[ee][2] + bo.z;
        out[(size_t)e * OUT_DIM + tx * 4 + 3] = acc[ee][3] + bo.w;
    }
}

// ---------------- launch ----------------
extern "C" void kernel_launch(void* const* d_in, const int* in_sizes, int n_in,
                              void* d_out, int out_size)
{
    (void)in_sizes; (void)n_in; (void)out_size;
    const float* node = (const float*)d_in[0];
    const float* inc  = (const float*)d_in[1];
    const float* W1   = (const float*)d_in[2];
    const float* b1   = (const float*)d_in[3];
    const float* Wa   = (const float*)d_in[4];
    const float* ba   = (const float*)d_in[5];
    const float* W2   = (const float*)d_in[6];
    const float* b2   = (const float*)d_in[7];
    const float* Wout = (const float*)d_in[8];
    const float* bout = (const float*)d_in[9];
    float* out = (float*)d_out;

    cudaFuncSetAttribute(k2_mma, cudaFuncAttributeMaxDynamicSharedMemorySize, K2_SMEM);
    cudaFuncSetAttribute(k1b_project, cudaFuncAttributeMaxDynamicSharedMemorySize, 69120);

    k0_init<<<64, 256>>>();
    k1_node_transform<<<dim3(N_NODES / 64, TCOLS / 64), 256>>>(node, W1, b1);
    k1b_project<<<dim3(N_NODES / 64, HEADS), 256, 69120>>>(W2, Wa);
    k2_mma<<<N_EDGES / 128, 256, K2_SMEM>>>(inc, ba);
    k4_softmax<<<HEADS, 1024>>>();
    k5_u<<<N_EDGES / 64, 256>>>(b2);
    k6_out<<<N_EDGES / 32, 256>>>(Wout, bout, out);
}